// round 11
// baseline (speedup 1.0000x reference)
#include <cuda_runtime.h>
#include <cuda_bf16.h>

#define HD    10
#define MSZ   41
#define HB    128        // A-tile rows / layout batch slots per block
#define HBL   111        // logical batch elems per block (148 blocks, 1 full wave)
#define TB    256        // threads per block
#define EST   129        // E row stride in float4
#define ERB   (EST*16)   // E row stride bytes = 2064
#define SPC   32         // s-slots per chunk (K=128 = 32*4)
#define NCHS  14         // s-feature chunks (S <= 448)
#define NCHE  2          // E chunks (64 slots >= 42)
#define NCH   (NCHS+NCHE)
#define SMAX  (NCHS*SPC) // 448
#define AST   272        // A/B smem row stride bytes (256 data + 16 pad)
#define DSTF  82         // D smem row stride in floats

// smem byte offsets (double-buffered A/B)
#define OFF_E    0
#define OFF_HDR  86688                 // 448 * 32B headers -> ends 101024
#define OFF_A0   101024                // 128 x 272 = 34816
#define OFF_B0   135840                // 40 x 272 = 10880 -> ends 146720
#define OFF_A1   146720
#define OFF_B1   181536                // -> ends 192416
#define DBUF     45696
#define OFF_D    OFF_A0                // overlay after GEMM (128 x 82 f32)
#define OFF_RED  OFF_A1                // overlay: 128 x 16B pbc partials
#define SMEM_TOT 192416

typedef unsigned int u32;

__device__ __align__(16) float         g_hdr[SMAX * 8];
__device__ __align__(16) __nv_bfloat16 g_W[NCH * 40 * 128];

static __device__ __forceinline__ u32 s2u(const void* p) {
    u32 a; asm("{ .reg .u64 t; cvta.to.shared.u64 t, %1; cvt.u32.u64 %0, t; }"
               : "=r"(a) : "l"(p));
    return a;
}
static __device__ __forceinline__ u32 bfpack(float lo, float hi) {
    u32 r; asm("cvt.rn.bf16x2.f32 %0, %1, %2;" : "=r"(r) : "f"(hi), "f"(lo));
    return r;
}

#define LDSM4(R0,R1,R2,R3,ADDR) \
    asm volatile("ldmatrix.sync.aligned.m8n8.x4.shared.b16 {%0,%1,%2,%3}, [%4];" \
        : "=r"(R0),"=r"(R1),"=r"(R2),"=r"(R3) : "r"(ADDR))
#define LDSM2(R0,R1,ADDR) \
    asm volatile("ldmatrix.sync.aligned.m8n8.x2.shared.b16 {%0,%1}, [%2];" \
        : "=r"(R0),"=r"(R1) : "r"(ADDR))
#define MMA16816(C0,C1,C2,C3,A0,A1,A2,A3,B0,B1) \
    asm volatile("mma.sync.aligned.m16n8k16.row.col.f32.bf16.bf16.f32 " \
        "{%0,%1,%2,%3},{%4,%5,%6,%7},{%8,%9},{%0,%1,%2,%3};" \
        : "+f"(C0),"+f"(C1),"+f"(C2),"+f"(C3) \
        : "r"(A0),"r"(A1),"r"(A2),"r"(A3),"r"(B0),"r"(B1))

#define MMA_CHUNK(ACC, OFFS) \
    for (int ks = 0; ks < 8; ks++) { \
        u32 A0,A1,A2,A3,B0,B1,B2,B3,B4,B5; \
        LDSM4(A0,A1,A2,A3, aAddr + (OFFS) + ks*32); \
        LDSM4(B0,B1,B2,B3, bAddr0 + (OFFS) + ks*32); \
        MMA16816(ACC[0],ACC[1],ACC[2],ACC[3],   A0,A1,A2,A3, B0,B1); \
        MMA16816(ACC[4],ACC[5],ACC[6],ACC[7],   A0,A1,A2,A3, B2,B3); \
        LDSM4(B0,B1,B2,B3, bAddr1 + (OFFS) + ks*32); \
        MMA16816(ACC[8],ACC[9],ACC[10],ACC[11], A0,A1,A2,A3, B0,B1); \
        MMA16816(ACC[12],ACC[13],ACC[14],ACC[15],A0,A1,A2,A3, B2,B3); \
        LDSM2(B4,B5, bAddr2 + (OFFS) + ks*32); \
        MMA16816(ACC[16],ACC[17],ACC[18],ACC[19],A0,A1,A2,A3, B4,B5); \
    }

// single merged prep: one thread per bf16 weight element; low threads also do headers
__global__ void prep_all(const float* __restrict__ pbc_C,
                         const float* __restrict__ W1,
                         const float* __restrict__ W2,
                         const int*   __restrict__ m_idx,
                         const int*   __restrict__ n_idx,
                         int S) {
    int j = blockIdx.x * blockDim.x + threadIdx.x;
    const int c0 = MSZ / 2;
    if (j < SMAX) {
        float* h = g_hdr + j * 8;
        bool v = (j < S);
        int m = v ? m_idx[j] : 0;
        int n = v ? n_idx[j] : 0;
        h[0] = __int_as_float(v ? (c0 + m) * ERB : 0);
        h[1] = __int_as_float(v ? (c0 + m + n) * ERB : 0);
        h[2] = __int_as_float(v ? (c0 + n) * ERB : 0);
        h[3] = 0.f;
        h[4] = v ? 0.5f * pbc_C[2 * j + 0] : 0.f;
        h[5] = v ? 0.5f * pbc_C[2 * j + 1] : 0.f;
        h[6] = 0.f; h[7] = 0.f;
    }
    if (j >= NCH * 40 * 128) return;
    int kk = j & 127;
    int n  = (j >> 7) % 40;
    int ch = j / (40 * 128);
    int o = n >> 2, cc = n & 3;
    int unit = kk >> 2, comp = kk & 3;
    bool isE = (ch >= NCHS);
    float f = 0.f;
    int idx, L; bool valid;
    if (!isE) { idx = ch * SPC + unit;          valid = (idx < S);   L = S;   }
    else      { idx = (ch - NCHS) * SPC + unit; valid = (idx < MSZ); L = MSZ; }
    if (valid) {
        const float* W = isE ? W2 : W1;
        float w0r = W[((2 * o) * L + idx) * 2 + 0];
        float w0i = W[((2 * o) * L + idx) * 2 + 1];
        float w1r = W[((2 * o + 1) * L + idx) * 2 + 0];
        float w1i = W[((2 * o + 1) * L + idx) * 2 + 1];
        float sr = 0.5f * (w0r + w1r), si = 0.5f * (w0i + w1i);
        float dr = 0.5f * (w0r - w1r), di = 0.5f * (w0i - w1i);
        if      (cc == 0) f = (comp == 0) ? sr : (comp == 1) ? -si : 0.f;
        else if (cc == 1) f = (comp == 0) ? si : (comp == 1) ?  sr : 0.f;
        else if (cc == 2) f = (comp == 2) ? dr : (comp == 3) ? -di : 0.f;
        else              f = (comp == 2) ? di : (comp == 3) ?  dr : 0.f;
    }
    g_W[(size_t)ch * 5120 + (size_t)n * 128 + kk] = __float2bfloat16(f);
}

__global__ __launch_bounds__(TB) void eqsonn_kernel(
    const float* __restrict__ x,
    const float* __restrict__ task,
    const float* __restrict__ b1g,
    const float* __restrict__ b2g,
    float* __restrict__ out,
    int Btot) {
    extern __shared__ char smc[];
    const u32 smb = s2u(smc);
    const int t    = threadIdx.x;
    const int half = t >> 7;
    const int tl   = t & (HB - 1);
    const int bbase = blockIdx.x * HBL;
    const int b    = bbase + tl;
    int nvalid = Btot - bbase;
    if (nvalid > HBL) nvalid = HBL;

    // headers into smem
    {
        const float4* src = (const float4*)g_hdr;
        float4* dst = (float4*)(smc + OFF_HDR);
        for (int i = t; i < SMAX * 2; i += TB) dst[i] = src[i];
    }
    // coalesced transposed E load (valid elems only); zero pad row 41 for all cols
    {
        float4* E4 = (float4*)(smc + OFF_E);
        const float4* xb = (const float4*)(x + (size_t)bbase * (MSZ * 4));
        int ntot = nvalid * MSZ;
        for (int i = t; i < ntot; i += TB) {
            int e = i / MSZ;
            int r = i - e * MSZ;
            E4[r * EST + e] = xb[i];
        }
        for (int i = t; i < HB; i += TB)
            E4[41 * EST + i] = make_float4(0.f, 0.f, 0.f, 0.f);
    }
    __syncthreads();

    const char* Eb = smc + OFF_E + tl * 16;
    float ps_r = 0.f, ps_i = 0.f, pd_r = 0.f, pd_i = 0.f;

    float acc1[20], acc2[20];
#pragma unroll
    for (int i = 0; i < 20; i++) { acc1[i] = 0.f; acc2[i] = 0.f; }

    // warp-level ldmatrix base addresses (buffer 0)
    const int warp = t >> 5, lane = t & 31;
    const int grp = lane >> 3, l7 = lane & 7;
    const u32 m0 = warp * 16;
    const u32 aAddr  = smb + OFF_A0 + (m0 + (grp & 1) * 8 + l7) * AST + (grp >> 1) * 16;
    const u32 bAddr0 = smb + OFF_B0 + ((grp >> 1) * 8 + l7) * AST + (grp & 1) * 16;
    const u32 bAddr1 = bAddr0 + 16 * AST;
    const u32 bAddr2 = smb + OFF_B0 + (32 + l7) * AST + (grp & 1) * 16;

#define STAGE_CHUNK(CI, BSEL) do {                                            \
        int c_ = (CI);                                                        \
        char* Bbase = smc + OFF_B0 + (BSEL) * DBUF;                           \
        const float4* srcW = (const float4*)(g_W + (size_t)c_ * 5120);        \
        for (int i = t; i < 640; i += TB) {                                   \
            int r_ = i >> 4, q_ = i & 15;                                     \
            *(float4*)(Bbase + r_ * AST + q_ * 16) = srcW[i];                 \
        }                                                                     \
        char* Ab = smc + OFF_A0 + (BSEL) * DBUF + tl * AST;                   \
        if (c_ < NCHS) {                                                      \
            const float4* hp = (const float4*)(smc + OFF_HDR)                 \
                             + (size_t)(c_ * SPC + half * 16) * 2;            \
            _Pragma("unroll")                                                 \
            for (int k8 = 0; k8 < 16; k8++) {                                 \
                float4 h0 = hp[2 * k8];                                       \
                float4 h1 = hp[2 * k8 + 1];                                   \
                float4 a = *(const float4*)(Eb + __float_as_int(h0.x));       \
                float4 q = *(const float4*)(Eb + __float_as_int(h0.y));       \
                float4 n = *(const float4*)(Eb + __float_as_int(h0.z));       \
                float Ar = a.x * q.x + a.y * q.y + a.z * q.z + a.w * q.w;     \
                float Ai = a.y * q.x - a.x * q.y + a.w * q.z - a.z * q.w;     \
                float nsr = n.x + n.z, nsi = n.y + n.w;                       \
                float ndr = n.x - n.z, ndi = n.y - n.w;                       \
                float Gsr = Ar * nsr - Ai * nsi, Gsi = Ar * nsi + Ai * nsr;   \
                float Gdr = Ar * ndr - Ai * ndi, Gdi = Ar * ndi + Ai * ndr;   \
                ps_r += Gsr * h1.x - Gsi * h1.y;  ps_i += Gsr * h1.y + Gsi * h1.x; \
                pd_r += Gdr * h1.x - Gdi * h1.y;  pd_i += Gdr * h1.y + Gdi * h1.x; \
                *(uint2*)(Ab + (half * 16 + k8) * 8) =                        \
                    make_uint2(bfpack(Gsr, Gsi), bfpack(Gdr, Gdi));           \
            }                                                                 \
        } else {                                                              \
            _Pragma("unroll")                                                 \
            for (int k8 = 0; k8 < 16; k8++) {                                 \
                int ks_ = (c_ - NCHS) * SPC + half * 16 + k8;                 \
                float4 v = (ks_ <= 41) ? *(const float4*)(Eb + ks_ * ERB)     \
                                       : make_float4(0.f, 0.f, 0.f, 0.f);     \
                *(uint2*)(Ab + (half * 16 + k8) * 8) =                        \
                    make_uint2(bfpack(v.x + v.z, v.y + v.w),                  \
                               bfpack(v.x - v.z, v.y - v.w));                 \
            }                                                                 \
        }                                                                     \
    } while (0)

    // prologue: stage chunk 0 into buffer 0
    STAGE_CHUNK(0, 0);
    __syncthreads();

    for (int c = 0; c < NCH; c++) {
        u32 offs = (u32)((c & 1) * DBUF);
        if (c < NCHS) { MMA_CHUNK(acc1, offs); }
        else          { MMA_CHUNK(acc2, offs); }
        if (c + 1 < NCH) STAGE_CHUNK(c + 1, (c + 1) & 1);
        __syncthreads();
    }

    // ---- write D fragments + pbc partials to smem ----
    float* Dsm = (float*)(smc + OFF_D);
    {
        int rr4 = lane >> 2;
        int cb2 = (lane & 3) * 2;
#pragma unroll
        for (int tau = 0; tau < 5; tau++) {
            int col = tau * 8 + cb2;
            *(float2*)&Dsm[(m0 + rr4) * DSTF + col]      = make_float2(acc1[4*tau],   acc1[4*tau+1]);
            *(float2*)&Dsm[(m0 + 8 + rr4) * DSTF + col]  = make_float2(acc1[4*tau+2], acc1[4*tau+3]);
            *(float2*)&Dsm[(m0 + rr4) * DSTF + 40 + col]     = make_float2(acc2[4*tau],   acc2[4*tau+1]);
            *(float2*)&Dsm[(m0 + 8 + rr4) * DSTF + 40 + col] = make_float2(acc2[4*tau+2], acc2[4*tau+3]);
        }
    }
    if (half) {
        float* d = (float*)(smc + OFF_RED) + tl * 4;
        d[0] = ps_r; d[1] = ps_i; d[2] = pd_r; d[3] = pd_i;
    }
    __syncthreads();

    // ---- epilogue (threads 0..127, valid batch rows only) ----
    if (half == 0 && tl < nvalid) {
        const float* rv = (const float*)(smc + OFF_RED) + tl * 4;
        ps_r += rv[0]; ps_i += rv[1]; pd_r += rv[2]; pd_i += rv[3];

        float tsk = task[(size_t)b * 4];
        float P = exp10f(tsk * 0.1f) * 0.5f;
        const float scl = 3.16227766016837939e-05f;  // 1e-4 / sqrt(10)
        float sc = scl * P * P;
        float4 Ec = *(const float4*)(Eb + 20 * ERB);

        const float* Dr = Dsm + (size_t)tl * DSTF;
        float tr0 = 0.f, ti0 = 0.f, tr1 = 0.f, ti1 = 0.f;
#pragma unroll
        for (int o = 0; o < HD; o++) {
            float b1r = b1g[2 * o], b1i = b1g[2 * o + 1];
            float b2r = b2g[2 * o], b2i = b2g[2 * o + 1];
            float asr_ = Dr[4 * o + 0], asi_ = Dr[4 * o + 1];
            float adr_ = Dr[4 * o + 2], adi_ = Dr[4 * o + 3];
            float bsr_ = Dr[40 + 4 * o + 0], bsi_ = Dr[40 + 4 * o + 1];
            float bdr_ = Dr[40 + 4 * o + 2], bdi_ = Dr[40 + 4 * o + 3];

            float ar = asr_ + adr_ + b1r, ai = asi_ + adi_ + b1i;
            float brv = bsr_ + bdr_ + b2r, biv = bsi_ + bdi_ + b2i;
            float rr = 2.f * (ar * brv + ai * biv);
            tr0 += rr * brv; ti0 += rr * biv;

            ar = asr_ - adr_ + b1r; ai = asi_ - adi_ + b1i;
            brv = bsr_ - bdr_ + b2r; biv = bsi_ - bdi_ + b2i;
            rr = 2.f * (ar * brv + ai * biv);
            tr1 += rr * brv; ti1 += rr * biv;
        }

        float4 res;
        res.x = Ec.x + P * (ps_r + pd_r) + sc * tr0;
        res.y = Ec.y + P * (ps_i + pd_i) + sc * ti0;
        res.z = Ec.z + P * (ps_r - pd_r) + sc * tr1;
        res.w = Ec.w + P * (ps_i - pd_i) + sc * ti1;
        *(float4*)(out + (size_t)b * 4) = res;
    }
}

extern "C" void kernel_launch(void* const* d_in, const int* in_sizes, int n_in,
                              void* d_out, int out_size) {
    const float* x     = (const float*)d_in[0];
    const float* task  = (const float*)d_in[1];
    const float* pbc_C = (const float*)d_in[2];
    const float* W1    = (const float*)d_in[3];
    const float* b1    = (const float*)d_in[4];
    const float* W2    = (const float*)d_in[5];
    const float* b2    = (const float*)d_in[6];
    const int*   m_idx = (const int*)d_in[7];
    const int*   n_idx = (const int*)d_in[8];
    int S = in_sizes[7];
    if (S > SMAX) S = SMAX;
    int B = out_size / 4;

    cudaFuncSetAttribute(eqsonn_kernel,
                         cudaFuncAttributeMaxDynamicSharedMemorySize, SMEM_TOT);

    prep_all<<<(NCH * 40 * 128 + 255) / 256, 256>>>(pbc_C, W1, W2, m_idx, n_idx, S);

    int blocks = (B + HBL - 1) / HBL;
    eqsonn_kernel<<<blocks, TB, SMEM_TOT>>>(x, task, b1, b2, (float*)d_out, B);
}

// round 12
// speedup vs baseline: 1.2346x; 1.2346x over previous
#include <cuda_runtime.h>
#include <cuda_bf16.h>

#define HD    10
#define MSZ   41
#define HB    128        // batch elems per block
#define TB    512        // threads per block: 4 quarters of 128
#define EST   129        // E row stride in float4
#define ERB   (EST*16)   // E row stride bytes = 2064
#define SPC   32         // s-slots per chunk (K=128 = 32*4)
#define NCHS  14         // s-feature chunks (S <= 448)
#define NCHE  2          // E chunks (64 slots >= 42)
#define NCH   (NCHS+NCHE)
#define SMAX  (NCHS*SPC) // 448
#define AST   272        // A/B smem row stride bytes
#define DSTF  82         // D smem row stride in floats

// smem byte offsets (double-buffered A/B)
#define OFF_E    0
#define OFF_HDR  86688
#define OFF_A0   101024
#define OFF_B0   135840
#define OFF_A1   146720
#define OFF_B1   181536
#define DBUF     45696
#define OFF_D    OFF_A0                // overlay after GEMM
#define OFF_RED  OFF_A1                // overlay: 3 x 128 x 16B pbc partials
#define SMEM_TOT 192416

typedef unsigned int u32;

__device__ __align__(16) float         g_hdr[SMAX * 8];
__device__ __align__(16) __nv_bfloat16 g_W[NCH * 40 * 128];

static __device__ __forceinline__ u32 s2u(const void* p) {
    u32 a; asm("{ .reg .u64 t; cvta.to.shared.u64 t, %1; cvt.u32.u64 %0, t; }"
               : "=r"(a) : "l"(p));
    return a;
}
static __device__ __forceinline__ u32 bfpack(float lo, float hi) {
    u32 r; asm("cvt.rn.bf16x2.f32 %0, %1, %2;" : "=r"(r) : "f"(hi), "f"(lo));
    return r;
}

#define LDSM4(R0,R1,R2,R3,ADDR) \
    asm volatile("ldmatrix.sync.aligned.m8n8.x4.shared.b16 {%0,%1,%2,%3}, [%4];" \
        : "=r"(R0),"=r"(R1),"=r"(R2),"=r"(R3) : "r"(ADDR))
#define LDSM2(R0,R1,ADDR) \
    asm volatile("ldmatrix.sync.aligned.m8n8.x2.shared.b16 {%0,%1}, [%2];" \
        : "=r"(R0),"=r"(R1) : "r"(ADDR))
#define MMA16816(C0,C1,C2,C3,A0,A1,A2,A3,B0,B1) \
    asm volatile("mma.sync.aligned.m16n8k16.row.col.f32.bf16.bf16.f32 " \
        "{%0,%1,%2,%3},{%4,%5,%6,%7},{%8,%9},{%0,%1,%2,%3};" \
        : "+f"(C0),"+f"(C1),"+f"(C2),"+f"(C3) \
        : "r"(A0),"r"(A1),"r"(A2),"r"(A3),"r"(B0),"r"(B1))

#define MMA_CHUNK(ACC, OFFS) \
    for (int ks = 0; ks < 8; ks++) { \
        u32 A0,A1,A2,A3,B0,B1,B2,B3,B4,B5; \
        LDSM4(A0,A1,A2,A3, aAddr + (OFFS) + ks*32); \
        LDSM4(B0,B1,B2,B3, bAddr0 + (OFFS) + ks*32); \
        MMA16816(ACC[0],ACC[1],ACC[2],ACC[3],   A0,A1,A2,A3, B0,B1); \
        MMA16816(ACC[4],ACC[5],ACC[6],ACC[7],   A0,A1,A2,A3, B2,B3); \
        LDSM4(B0,B1,B2,B3, bAddr1 + (OFFS) + ks*32); \
        MMA16816(ACC[8],ACC[9],ACC[10],ACC[11], A0,A1,A2,A3, B0,B1); \
        MMA16816(ACC[12],ACC[13],ACC[14],ACC[15],A0,A1,A2,A3, B2,B3); \
        LDSM2(B4,B5, bAddr2 + (OFFS) + ks*32); \
        MMA16816(ACC[16],ACC[17],ACC[18],ACC[19],A0,A1,A2,A3, B4,B5); \
    }

// merged prep: one thread per bf16 weight element; low threads also do headers
__global__ void prep_all(const float* __restrict__ pbc_C,
                         const float* __restrict__ W1,
                         const float* __restrict__ W2,
                         const int*   __restrict__ m_idx,
                         const int*   __restrict__ n_idx,
                         int S) {
    int j = blockIdx.x * blockDim.x + threadIdx.x;
    const int c0 = MSZ / 2;
    if (j < SMAX) {
        float* h = g_hdr + j * 8;
        bool v = (j < S);
        int m = v ? m_idx[j] : 0;
        int n = v ? n_idx[j] : 0;
        h[0] = __int_as_float(v ? (c0 + m) * ERB : 0);
        h[1] = __int_as_float(v ? (c0 + m + n) * ERB : 0);
        h[2] = __int_as_float(v ? (c0 + n) * ERB : 0);
        h[3] = 0.f;
        h[4] = v ? 0.5f * pbc_C[2 * j + 0] : 0.f;
        h[5] = v ? 0.5f * pbc_C[2 * j + 1] : 0.f;
        h[6] = 0.f; h[7] = 0.f;
    }
    if (j >= NCH * 40 * 128) return;
    int kk = j & 127;
    int n  = (j >> 7) % 40;
    int ch = j / (40 * 128);
    int o = n >> 2, cc = n & 3;
    int unit = kk >> 2, comp = kk & 3;
    bool isE = (ch >= NCHS);
    float f = 0.f;
    int idx, L; bool valid;
    if (!isE) { idx = ch * SPC + unit;          valid = (idx < S);   L = S;   }
    else      { idx = (ch - NCHS) * SPC + unit; valid = (idx < MSZ); L = MSZ; }
    if (valid) {
        const float* W = isE ? W2 : W1;
        float w0r = W[((2 * o) * L + idx) * 2 + 0];
        float w0i = W[((2 * o) * L + idx) * 2 + 1];
        float w1r = W[((2 * o + 1) * L + idx) * 2 + 0];
        float w1i = W[((2 * o + 1) * L + idx) * 2 + 1];
        float sr = 0.5f * (w0r + w1r), si = 0.5f * (w0i + w1i);
        float dr = 0.5f * (w0r - w1r), di = 0.5f * (w0i - w1i);
        if      (cc == 0) f = (comp == 0) ? sr : (comp == 1) ? -si : 0.f;
        else if (cc == 1) f = (comp == 0) ? si : (comp == 1) ?  sr : 0.f;
        else if (cc == 2) f = (comp == 2) ? dr : (comp == 3) ? -di : 0.f;
        else              f = (comp == 2) ? di : (comp == 3) ?  dr : 0.f;
    }
    g_W[(size_t)ch * 5120 + (size_t)n * 128 + kk] = __float2bfloat16(f);
}

__global__ __launch_bounds__(TB) void eqsonn_kernel(
    const float* __restrict__ x,
    const float* __restrict__ task,
    const float* __restrict__ b1g,
    const float* __restrict__ b2g,
    float* __restrict__ out,
    int Btot) {
    extern __shared__ char smc[];
    const u32 smb = s2u(smc);
    const int t  = threadIdx.x;
    const int q  = t >> 7;          // quarter 0..3
    const int tl = t & (HB - 1);    // batch row within block
    const int b  = blockIdx.x * HB + tl;

    // headers into smem (all 512 threads)
    {
        const float4* src = (const float4*)g_hdr;
        float4* dst = (float4*)(smc + OFF_HDR);
        for (int i = t; i < SMAX * 2; i += TB) dst[i] = src[i];
    }
    // coalesced transposed E load; zero pad row 41
    {
        float4* E4 = (float4*)(smc + OFF_E);
        const float4* xb = (const float4*)(x + (size_t)blockIdx.x * HB * (MSZ * 4));
        for (int i = t; i < HB * MSZ; i += TB) {
            int e = i / MSZ;
            int r = i - e * MSZ;
            E4[r * EST + e] = xb[i];
        }
        for (int i = t; i < HB; i += TB)
            E4[41 * EST + i] = make_float4(0.f, 0.f, 0.f, 0.f);
    }
    __syncthreads();

    const char* Eb = smc + OFF_E + tl * 16;
    float ps_r = 0.f, ps_i = 0.f, pd_r = 0.f, pd_i = 0.f;

    float acc1[20], acc2[20];
#pragma unroll
    for (int i = 0; i < 20; i++) { acc1[i] = 0.f; acc2[i] = 0.f; }

    // MMA addressing (quarters 0-1 only; warps 0..7)
    const int warp = t >> 5, lane = t & 31;
    const int grp = lane >> 3, l7 = lane & 7;
    const u32 m0 = (warp & 7) * 16;
    const u32 aAddr  = smb + OFF_A0 + (m0 + (grp & 1) * 8 + l7) * AST + (grp >> 1) * 16;
    const u32 bAddr0 = smb + OFF_B0 + ((grp >> 1) * 8 + l7) * AST + (grp & 1) * 16;
    const u32 bAddr1 = bAddr0 + 16 * AST;
    const u32 bAddr2 = smb + OFF_B0 + (32 + l7) * AST + (grp & 1) * 16;

    // k-slot ranges: stagers (q=2,3) take [0,24); MMA threads (q=0,1) take [24,32)
    const int myk0 = (q >= 2) ? (q - 2) * 12 : 24 + q * 4;
    const int myk1 = (q >= 2) ? myk0 + 12    : myk0 + 4;

#define STAGE_B(CI, BSEL) do {                                                \
        char* Bbase = smc + OFF_B0 + (BSEL) * DBUF;                           \
        const float4* srcW = (const float4*)(g_W + (size_t)(CI) * 5120);      \
        for (int i = t & 255; i < 640; i += 256) {                            \
            int r_ = i >> 4, q_ = i & 15;                                     \
            *(float4*)(Bbase + r_ * AST + q_ * 16) = srcW[i];                 \
        }                                                                     \
    } while (0)

#define STAGE_A(CI, BSEL, K0, K1) do {                                        \
        int c_ = (CI);                                                        \
        char* Ab = smc + OFF_A0 + (BSEL) * DBUF + tl * AST;                   \
        if (c_ < NCHS) {                                                      \
            const float4* hp = (const float4*)(smc + OFF_HDR)                 \
                             + (size_t)(c_ * SPC) * 2;                        \
            _Pragma("unroll")                                                 \
            for (int k = (K0); k < (K1); k++) {                               \
                float4 h0 = hp[2 * k];                                        \
                float4 h1 = hp[2 * k + 1];                                    \
                float4 a = *(const float4*)(Eb + __float_as_int(h0.x));       \
                float4 qq = *(const float4*)(Eb + __float_as_int(h0.y));      \
                float4 n = *(const float4*)(Eb + __float_as_int(h0.z));       \
                float Ar = a.x * qq.x + a.y * qq.y + a.z * qq.z + a.w * qq.w; \
                float Ai = a.y * qq.x - a.x * qq.y + a.w * qq.z - a.z * qq.w; \
                float nsr = n.x + n.z, nsi = n.y + n.w;                       \
                float ndr = n.x - n.z, ndi = n.y - n.w;                       \
                float Gsr = Ar * nsr - Ai * nsi, Gsi = Ar * nsi + Ai * nsr;   \
                float Gdr = Ar * ndr - Ai * ndi, Gdi = Ar * ndi + Ai * ndr;   \
                ps_r += Gsr * h1.x - Gsi * h1.y;  ps_i += Gsr * h1.y + Gsi * h1.x; \
                pd_r += Gdr * h1.x - Gdi * h1.y;  pd_i += Gdr * h1.y + Gdi * h1.x; \
                *(uint2*)(Ab + k * 8) =                                       \
                    make_uint2(bfpack(Gsr, Gsi), bfpack(Gdr, Gdi));           \
            }                                                                 \
        } else {                                                              \
            _Pragma("unroll")                                                 \
            for (int k = (K0); k < (K1); k++) {                               \
                int ks_ = (c_ - NCHS) * SPC + k;                              \
                float4 v = (ks_ <= 41) ? *(const float4*)(Eb + ks_ * ERB)     \
                                       : make_float4(0.f, 0.f, 0.f, 0.f);     \
                *(uint2*)(Ab + k * 8) =                                       \
                    make_uint2(bfpack(v.x + v.z, v.y + v.w),                  \
                               bfpack(v.x - v.z, v.y - v.w));                 \
            }                                                                 \
        }                                                                     \
    } while (0)

    // prologue: everyone stages chunk 0 (buffer 0)
    if (q < 2) STAGE_B(0, 0);
    STAGE_A(0, 0, myk0, myk1);
    __syncthreads();

    for (int c = 0; c < NCH; c++) {
        u32 offs = (u32)((c & 1) * DBUF);
        if (q < 2) {
            if (c + 1 < NCH) STAGE_B(c + 1, (c + 1) & 1);
            if (c < NCHS) { MMA_CHUNK(acc1, offs); }
            else          { MMA_CHUNK(acc2, offs); }
            if (c + 1 < NCH) STAGE_A(c + 1, (c + 1) & 1, myk0, myk1);
        } else {
            if (c + 1 < NCH) STAGE_A(c + 1, (c + 1) & 1, myk0, myk1);
        }
        __syncthreads();
    }

    // ---- write D fragments (MMA warps) + pbc partials (quarters 1-3) ----
    float* Dsm = (float*)(smc + OFF_D);
    if (q < 2) {
        int rr4 = lane >> 2;
        int cb2 = (lane & 3) * 2;
#pragma unroll
        for (int tau = 0; tau < 5; tau++) {
            int col = tau * 8 + cb2;
            *(float2*)&Dsm[(m0 + rr4) * DSTF + col]      = make_float2(acc1[4*tau],   acc1[4*tau+1]);
            *(float2*)&Dsm[(m0 + 8 + rr4) * DSTF + col]  = make_float2(acc1[4*tau+2], acc1[4*tau+3]);
            *(float2*)&Dsm[(m0 + rr4) * DSTF + 40 + col]     = make_float2(acc2[4*tau],   acc2[4*tau+1]);
            *(float2*)&Dsm[(m0 + 8 + rr4) * DSTF + 40 + col] = make_float2(acc2[4*tau+2], acc2[4*tau+3]);
        }
    }
    if (q >= 1) {
        float* d = (float*)(smc + OFF_RED) + ((q - 1) * HB + tl) * 4;
        d[0] = ps_r; d[1] = ps_i; d[2] = pd_r; d[3] = pd_i;
    }
    __syncthreads();

    // ---- epilogue (quarter 0, valid rows) ----
    if (q == 0 && b < Btot) {
#pragma unroll
        for (int p = 0; p < 3; p++) {
            const float* rv = (const float*)(smc + OFF_RED) + (p * HB + tl) * 4;
            ps_r += rv[0]; ps_i += rv[1]; pd_r += rv[2]; pd_i += rv[3];
        }

        float tsk = task[(size_t)b * 4];
        float P = exp10f(tsk * 0.1f) * 0.5f;
        const float scl = 3.16227766016837939e-05f;  // 1e-4 / sqrt(10)
        float sc = scl * P * P;
        float4 Ec = *(const float4*)(Eb + 20 * ERB);

        const float* Dr = Dsm + (size_t)tl * DSTF;
        float tr0 = 0.f, ti0 = 0.f, tr1 = 0.f, ti1 = 0.f;
#pragma unroll
        for (int o = 0; o < HD; o++) {
            float b1r = b1g[2 * o], b1i = b1g[2 * o + 1];
            float b2r = b2g[2 * o], b2i = b2g[2 * o + 1];
            float asr_ = Dr[4 * o + 0], asi_ = Dr[4 * o + 1];
            float adr_ = Dr[4 * o + 2], adi_ = Dr[4 * o + 3];
            float bsr_ = Dr[40 + 4 * o + 0], bsi_ = Dr[40 + 4 * o + 1];
            float bdr_ = Dr[40 + 4 * o + 2], bdi_ = Dr[40 + 4 * o + 3];

            float ar = asr_ + adr_ + b1r, ai = asi_ + adi_ + b1i;
            float brv = bsr_ + bdr_ + b2r, biv = bsi_ + bdi_ + b2i;
            float rr = 2.f * (ar * brv + ai * biv);
            tr0 += rr * brv; ti0 += rr * biv;

            ar = asr_ - adr_ + b1r; ai = asi_ - adi_ + b1i;
            brv = bsr_ - bdr_ + b2r; biv = bsi_ - bdi_ + b2i;
            rr = 2.f * (ar * brv + ai * biv);
            tr1 += rr * brv; ti1 += rr * biv;
        }

        float4 res;
        res.x = Ec.x + P * (ps_r + pd_r) + sc * tr0;
        res.y = Ec.y + P * (ps_i + pd_i) + sc * ti0;
        res.z = Ec.z + P * (ps_r - pd_r) + sc * tr1;
        res.w = Ec.w + P * (ps_i - pd_i) + sc * ti1;
        *(float4*)(out + (size_t)b * 4) = res;
    }
}

extern "C" void kernel_launch(void* const* d_in, const int* in_sizes, int n_in,
                              void* d_out, int out_size) {
    const float* x     = (const float*)d_in[0];
    const float* task  = (const float*)d_in[1];
    const float* pbc_C = (const float*)d_in[2];
    const float* W1    = (const float*)d_in[3];
    const float* b1    = (const float*)d_in[4];
    const float* W2    = (const float*)d_in[5];
    const float* b2    = (const float*)d_in[6];
    const int*   m_idx = (const int*)d_in[7];
    const int*   n_idx = (const int*)d_in[8];
    int S = in_sizes[7];
    if (S > SMAX) S = SMAX;
    int B = out_size / 4;

    cudaFuncSetAttribute(eqsonn_kernel,
                         cudaFuncAttributeMaxDynamicSharedMemorySize, SMEM_TOT);

    prep_all<<<(NCH * 40 * 128 + 255) / 256, 256>>>(pbc_C, W1, W2, m_idx, n_idx, S);

    int blocks = (B + HB - 1) / HB;
    eqsonn_kernel<<<blocks, TB, SMEM_TOT>>>(x, task, b1, b2, (float*)d_out, B);
}

// round 14
// speedup vs baseline: 1.2965x; 1.0502x over previous
#include <cuda_runtime.h>
#include <cuda_bf16.h>

#define HD    10
#define MSZ   41
#define HB    128        // batch elems per block
#define TB    768        // threads per block: 6 groups of 128
#define EST   129        // E row stride in float4
#define ERB   (EST*16)   // E row stride bytes = 2064
#define SPC   32         // s-slots per chunk (K=128 = 32*4)
#define NCHS  14         // s-feature chunks (S <= 448)
#define NCHE  2          // E chunks (64 slots >= 42)
#define NCH   (NCHS+NCHE)
#define SMAX  (NCHS*SPC) // 448
#define AST   272        // A/B smem row stride bytes
#define DSTF  82         // D smem row stride in floats

// smem byte offsets (double-buffered A/B)
#define OFF_E    0
#define OFF_HDR  86688
#define OFF_A0   101024
#define OFF_B0   135840
#define OFF_A1   146720
#define OFF_B1   181536
#define DBUF     45696
#define OFF_D    OFF_A0                // overlay after GEMM
#define OFF_RED  OFF_A1                // overlay: 5 x 128 x 16B pbc partials
#define SMEM_TOT 192416

typedef unsigned int u32;

__device__ __align__(16) float         g_hdr[SMAX * 8];
__device__ __align__(16) __nv_bfloat16 g_W[NCH * 40 * 128];

static __device__ __forceinline__ u32 s2u(const void* p) {
    u32 a; asm("{ .reg .u64 t; cvta.to.shared.u64 t, %1; cvt.u32.u64 %0, t; }"
               : "=r"(a) : "l"(p));
    return a;
}
static __device__ __forceinline__ u32 bfpack(float lo, float hi) {
    u32 r; asm("cvt.rn.bf16x2.f32 %0, %1, %2;" : "=r"(r) : "f"(hi), "f"(lo));
    return r;
}

#define LDSM4(R0,R1,R2,R3,ADDR) \
    asm volatile("ldmatrix.sync.aligned.m8n8.x4.shared.b16 {%0,%1,%2,%3}, [%4];" \
        : "=r"(R0),"=r"(R1),"=r"(R2),"=r"(R3) : "r"(ADDR))
#define LDSM2(R0,R1,ADDR) \
    asm volatile("ldmatrix.sync.aligned.m8n8.x2.shared.b16 {%0,%1}, [%2];" \
        : "=r"(R0),"=r"(R1) : "r"(ADDR))
#define MMA16816(C0,C1,C2,C3,A0,A1,A2,A3,B0,B1) \
    asm volatile("mma.sync.aligned.m16n8k16.row.col.f32.bf16.bf16.f32 " \
        "{%0,%1,%2,%3},{%4,%5,%6,%7},{%8,%9},{%0,%1,%2,%3};" \
        : "+f"(C0),"+f"(C1),"+f"(C2),"+f"(C3) \
        : "r"(A0),"r"(A1),"r"(A2),"r"(A3),"r"(B0),"r"(B1))

#define MMA_CHUNK(ACC, OFFS) \
    for (int ks = 0; ks < 8; ks++) { \
        u32 A0,A1,A2,A3,B0,B1,B2,B3,B4,B5; \
        LDSM4(A0,A1,A2,A3, aAddr + (OFFS) + ks*32); \
        LDSM4(B0,B1,B2,B3, bAddr0 + (OFFS) + ks*32); \
        MMA16816(ACC[0],ACC[1],ACC[2],ACC[3],   A0,A1,A2,A3, B0,B1); \
        MMA16816(ACC[4],ACC[5],ACC[6],ACC[7],   A0,A1,A2,A3, B2,B3); \
        LDSM4(B0,B1,B2,B3, bAddr1 + (OFFS) + ks*32); \
        MMA16816(ACC[8],ACC[9],ACC[10],ACC[11], A0,A1,A2,A3, B0,B1); \
        MMA16816(ACC[12],ACC[13],ACC[14],ACC[15],A0,A1,A2,A3, B2,B3); \
        LDSM2(B4,B5, bAddr2 + (OFFS) + ks*32); \
        MMA16816(ACC[16],ACC[17],ACC[18],ACC[19],A0,A1,A2,A3, B4,B5); \
    }

// merged prep: one thread per bf16 weight element; low threads also do headers
__global__ void prep_all(const float* __restrict__ pbc_C,
                         const float* __restrict__ W1,
                         const float* __restrict__ W2,
                         const int*   __restrict__ m_idx,
                         const int*   __restrict__ n_idx,
                         int S) {
    int j = blockIdx.x * blockDim.x + threadIdx.x;
    const int c0 = MSZ / 2;
    if (j < SMAX) {
        float* h = g_hdr + j * 8;
        bool v = (j < S);
        int m = v ? m_idx[j] : 0;
        int n = v ? n_idx[j] : 0;
        h[0] = __int_as_float(v ? (c0 + m) * ERB : 0);
        h[1] = __int_as_float(v ? (c0 + m + n) * ERB : 0);
        h[2] = __int_as_float(v ? (c0 + n) * ERB : 0);
        h[3] = 0.f;
        h[4] = v ? 0.5f * pbc_C[2 * j + 0] : 0.f;
        h[5] = v ? 0.5f * pbc_C[2 * j + 1] : 0.f;
        h[6] = 0.f; h[7] = 0.f;
    }
    if (j >= NCH * 40 * 128) return;
    int kk = j & 127;
    int n  = (j >> 7) % 40;
    int ch = j / (40 * 128);
    int o = n >> 2, cc = n & 3;
    int unit = kk >> 2, comp = kk & 3;
    bool isE = (ch >= NCHS);
    float f = 0.f;
    int idx, L; bool valid;
    if (!isE) { idx = ch * SPC + unit;          valid = (idx < S);   L = S;   }
    else      { idx = (ch - NCHS) * SPC + unit; valid = (idx < MSZ); L = MSZ; }
    if (valid) {
        const float* W = isE ? W2 : W1;
        float w0r = W[((2 * o) * L + idx) * 2 + 0];
        float w0i = W[((2 * o) * L + idx) * 2 + 1];
        float w1r = W[((2 * o + 1) * L + idx) * 2 + 0];
        float w1i = W[((2 * o + 1) * L + idx) * 2 + 1];
        float sr = 0.5f * (w0r + w1r), si = 0.5f * (w0i + w1i);
        float dr = 0.5f * (w0r - w1r), di = 0.5f * (w0i - w1i);
        if      (cc == 0) f = (comp == 0) ? sr : (comp == 1) ? -si : 0.f;
        else if (cc == 1) f = (comp == 0) ? si : (comp == 1) ?  sr : 0.f;
        else if (cc == 2) f = (comp == 2) ? dr : (comp == 3) ? -di : 0.f;
        else              f = (comp == 2) ? di : (comp == 3) ?  dr : 0.f;
    }
    g_W[(size_t)ch * 5120 + (size_t)n * 128 + kk] = __float2bfloat16(f);
}

__global__ __launch_bounds__(TB) void eqsonn_kernel(
    const float* __restrict__ x,
    const float* __restrict__ task,
    const float* __restrict__ b1g,
    const float* __restrict__ b2g,
    float* __restrict__ out,
    int Btot) {
    extern __shared__ char smc[];
    const u32 smb = s2u(smc);
    const int t  = threadIdx.x;
    const int q  = t >> 7;          // group 0..5
    const int tl = t & (HB - 1);    // batch row within block
    const int b  = blockIdx.x * HB + tl;

    // headers into smem (all threads)
    {
        const float4* src = (const float4*)g_hdr;
        float4* dst = (float4*)(smc + OFF_HDR);
        for (int i = t; i < SMAX * 2; i += TB) dst[i] = src[i];
    }
    // coalesced transposed E load; zero pad row 41
    {
        float4* E4 = (float4*)(smc + OFF_E);
        const float4* xb = (const float4*)(x + (size_t)blockIdx.x * HB * (MSZ * 4));
        for (int i = t; i < HB * MSZ; i += TB) {
            int e = i / MSZ;
            int r = i - e * MSZ;
            E4[r * EST + e] = xb[i];
        }
        for (int i = t; i < HB; i += TB)
            E4[41 * EST + i] = make_float4(0.f, 0.f, 0.f, 0.f);
    }
    __syncthreads();

    const char* Eb = smc + OFF_E + tl * 16;
    float ps_r = 0.f, ps_i = 0.f, pd_r = 0.f, pd_i = 0.f;

    float acc1[20], acc2[20];
#pragma unroll
    for (int i = 0; i < 20; i++) { acc1[i] = 0.f; acc2[i] = 0.f; }

    // MMA addressing (groups 0-1 = warps 0..7)
    const int warp = t >> 5, lane = t & 31;
    const int grp = lane >> 3, l7 = lane & 7;
    const u32 m0 = (warp & 7) * 16;
    const u32 aAddr  = smb + OFF_A0 + (m0 + (grp & 1) * 8 + l7) * AST + (grp >> 1) * 16;
    const u32 bAddr0 = smb + OFF_B0 + ((grp >> 1) * 8 + l7) * AST + (grp & 1) * 16;
    const u32 bAddr1 = bAddr0 + 16 * AST;
    const u32 bAddr2 = smb + OFF_B0 + (32 + l7) * AST + (grp & 1) * 16;

    // k-slot split: stagers (q=2..5) take 7 each -> [0,28); MMA groups take 2 each -> [28,32)
    const int myk0 = (q >= 2) ? (q - 2) * 7 : 28 + q * 2;
    const int myk1 = (q >= 2) ? myk0 + 7    : myk0 + 2;

#define STAGE_B(CI, BSEL) do {                                                \
        char* Bbase = smc + OFF_B0 + (BSEL) * DBUF;                           \
        const float4* srcW = (const float4*)(g_W + (size_t)(CI) * 5120);      \
        for (int i = t & 255; i < 640; i += 256) {                            \
            int r_ = i >> 4, q_ = i & 15;                                     \
            *(float4*)(Bbase + r_ * AST + q_ * 16) = srcW[i];                 \
        }                                                                     \
    } while (0)

#define STAGE_A(CI, BSEL, K0, K1) do {                                        \
        int c_ = (CI);                                                        \
        char* Ab = smc + OFF_A0 + (BSEL) * DBUF + tl * AST;                   \
        if (c_ < NCHS) {                                                      \
            const float4* hp = (const float4*)(smc + OFF_HDR)                 \
                             + (size_t)(c_ * SPC) * 2;                        \
            _Pragma("unroll")                                                 \
            for (int k = (K0); k < (K1); k++) {                               \
                float4 h0 = hp[2 * k];                                        \
                float4 h1 = hp[2 * k + 1];                                    \
                float4 a = *(const float4*)(Eb + __float_as_int(h0.x));       \
                float4 qq = *(const float4*)(Eb + __float_as_int(h0.y));      \
                float4 n = *(const float4*)(Eb + __float_as_int(h0.z));       \
                float Ar = a.x * qq.x + a.y * qq.y + a.z * qq.z + a.w * qq.w; \
                float Ai = a.y * qq.x - a.x * qq.y + a.w * qq.z - a.z * qq.w; \
                float nsr = n.x + n.z, nsi = n.y + n.w;                       \
                float ndr = n.x - n.z, ndi = n.y - n.w;                       \
                float Gsr = Ar * nsr - Ai * nsi, Gsi = Ar * nsi + Ai * nsr;   \
                float Gdr = Ar * ndr - Ai * ndi, Gdi = Ar * ndi + Ai * ndr;   \
                ps_r += Gsr * h1.x - Gsi * h1.y;  ps_i += Gsr * h1.y + Gsi * h1.x; \
                pd_r += Gdr * h1.x - Gdi * h1.y;  pd_i += Gdr * h1.y + Gdi * h1.x; \
                *(uint2*)(Ab + k * 8) =                                       \
                    make_uint2(bfpack(Gsr, Gsi), bfpack(Gdr, Gdi));           \
            }                                                                 \
        } else {                                                              \
            _Pragma("unroll")                                                 \
            for (int k = (K0); k < (K1); k++) {                               \
                int ks_ = (c_ - NCHS) * SPC + k;                              \
                float4 v = (ks_ <= 41) ? *(const float4*)(Eb + ks_ * ERB)     \
                                       : make_float4(0.f, 0.f, 0.f, 0.f);     \
                *(uint2*)(Ab + k * 8) =                                       \
                    make_uint2(bfpack(v.x + v.z, v.y + v.w),                  \
                               bfpack(v.x - v.z, v.y - v.w));                 \
            }                                                                 \
        }                                                                     \
    } while (0)

    // prologue: stage chunk 0 (buffer 0)
    if (q < 2) STAGE_B(0, 0);
    STAGE_A(0, 0, myk0, myk1);
    __syncthreads();

    for (int c = 0; c < NCH; c++) {
        u32 offs = (u32)((c & 1) * DBUF);
        if (q < 2) {
            if (c + 1 < NCH) STAGE_B(c + 1, (c + 1) & 1);
            if (c < NCHS) { MMA_CHUNK(acc1, offs); }
            else          { MMA_CHUNK(acc2, offs); }
            if (c + 1 < NCH) STAGE_A(c + 1, (c + 1) & 1, myk0, myk1);
        } else {
            if (c + 1 < NCH) STAGE_A(c + 1, (c + 1) & 1, myk0, myk1);
        }
        __syncthreads();
    }

    // ---- write D fragments (MMA warps) + pbc partials (groups 1-5) ----
    float* Dsm = (float*)(smc + OFF_D);
    if (q < 2) {
        int rr4 = lane >> 2;
        int cb2 = (lane & 3) * 2;
#pragma unroll
        for (int tau = 0; tau < 5; tau++) {
            int col = tau * 8 + cb2;
            *(float2*)&Dsm[(m0 + rr4) * DSTF + col]      = make_float2(acc1[4*tau],   acc1[4*tau+1]);
            *(float2*)&Dsm[(m0 + 8 + rr4) * DSTF + col]  = make_float2(acc1[4*tau+2], acc1[4*tau+3]);
            *(float2*)&Dsm[(m0 + rr4) * DSTF + 40 + col]     = make_float2(acc2[4*tau],   acc2[4*tau+1]);
            *(float2*)&Dsm[(m0 + 8 + rr4) * DSTF + 40 + col] = make_float2(acc2[4*tau+2], acc2[4*tau+3]);
        }
    }
    if (q >= 1) {
        float* d = (float*)(smc + OFF_RED) + ((q - 1) * HB + tl) * 4;
        d[0] = ps_r; d[1] = ps_i; d[2] = pd_r; d[3] = pd_i;
    }
    __syncthreads();

    // ---- epilogue (group 0, valid rows) ----
    if (q == 0 && b < Btot) {
#pragma unroll
        for (int p = 0; p < 5; p++) {
            const float* rv = (const float*)(smc + OFF_RED) + (p * HB + tl) * 4;
            ps_r += rv[0]; ps_i += rv[1]; pd_r += rv[2]; pd_i += rv[3];
        }

        float tsk = task[(size_t)b * 4];
        float P = exp10f(tsk * 0.1f) * 0.5f;
        const float scl = 3.16227766016837939e-05f;  // 1e-4 / sqrt(10)
        float sc = scl * P * P;
        float4 Ec = *(const float4*)(Eb + 20 * ERB);

        const float* Dr = Dsm + (size_t)tl * DSTF;
        float tr0 = 0.f, ti0 = 0.f, tr1 = 0.f, ti1 = 0.f;
#pragma unroll
        for (int o = 0; o < HD; o++) {
            float b1r = b1g[2 * o], b1i = b1g[2 * o + 1];
            float b2r = b2g[2 * o], b2i = b2g[2 * o + 1];
            float asr_ = Dr[4 * o + 0], asi_ = Dr[4 * o + 1];
            float adr_ = Dr[4 * o + 2], adi_ = Dr[4 * o + 3];
            float bsr_ = Dr[40 + 4 * o + 0], bsi_ = Dr[40 + 4 * o + 1];
            float bdr_ = Dr[40 + 4 * o + 2], bdi_ = Dr[40 + 4 * o + 3];

            float ar = asr_ + adr_ + b1r, ai = asi_ + adi_ + b1i;
            float brv = bsr_ + bdr_ + b2r, biv = bsi_ + bdi_ + b2i;
            float rr = 2.f * (ar * brv + ai * biv);
            tr0 += rr * brv; ti0 += rr * biv;

            ar = asr_ - adr_ + b1r; ai = asi_ - adi_ + b1i;
            brv = bsr_ - bdr_ + b2r; biv = bsi_ - bdi_ + b2i;
            rr = 2.f * (ar * brv + ai * biv);
            tr1 += rr * brv; ti1 += rr * biv;
        }

        float4 res;
        res.x = Ec.x + P * (ps_r + pd_r) + sc * tr0;
        res.y = Ec.y + P * (ps_i + pd_i) + sc * ti0;
        res.z = Ec.z + P * (ps_r - pd_r) + sc * tr1;
        res.w = Ec.w + P * (ps_i - pd_i) + sc * ti1;
        *(float4*)(out + (size_t)b * 4) = res;
    }
}

extern "C" void kernel_launch(void* const* d_in, const int* in_sizes, int n_in,
                              void* d_out, int out_size) {
    const float* x     = (const float*)d_in[0];
    const float* task  = (const float*)d_in[1];
    const float* pbc_C = (const float*)d_in[2];
    const float* W1    = (const float*)d_in[3];
    const float* b1    = (const float*)d_in[4];
    const float* W2    = (const float*)d_in[5];
    const float* b2    = (const float*)d_in[6];
    const int*   m_idx = (const int*)d_in[7];
    const int*   n_idx = (const int*)d_in[8];
    int S = in_sizes[7];
    if (S > SMAX) S = SMAX;
    int B = out_size / 4;

    cudaFuncSetAttribute(eqsonn_kernel,
                         cudaFuncAttributeMaxDynamicSharedMemorySize, SMEM_TOT);

    prep_all<<<(NCH * 40 * 128 + 255) / 256, 256>>>(pbc_C, W1, W2, m_idx, n_idx, S);

    int blocks = (B + HB - 1) / HB;
    eqsonn_kernel<<<blocks, TB, SMEM_TOT>>>(x, task, b1, b2, (float*)d_out, B);
}